// round 2
// baseline (speedup 1.0000x reference)
#include <cuda_runtime.h>
#include <cuda_bf16.h>

#define N_NODES 10000
#define N_EDGES 640000
#define C 128

// Scratch (device globals — no allocation allowed in kernel_launch)
__device__ int   g_deg_row[N_NODES];
__device__ int   g_deg_col[N_NODES];
__device__ float g_rrow[N_NODES];
__device__ float g_rcol[N_NODES];
__device__ float g_acc[N_NODES * C];

__device__ __forceinline__ float gelu_exact(float v) {
    return 0.5f * v * (1.0f + erff(v * 0.70710678118654752440f));
}

// K0: degree init = 1 (self loop)
__global__ void k0_init_deg() {
    int i = blockIdx.x * blockDim.x + threadIdx.x;
    if (i < N_NODES) { g_deg_row[i] = 1; g_deg_col[i] = 1; }
}

// K1: degree histogram over edges
__global__ void k1_deg(const int* __restrict__ ei) {
    int e = blockIdx.x * blockDim.x + threadIdx.x;
    if (e < N_EDGES) {
        int r = __ldg(ei + e);
        int c = __ldg(ei + N_EDGES + e);
        atomicAdd(&g_deg_row[r], 1);
        atomicAdd(&g_deg_col[c], 1);
    }
}

// K2: norm arrays + accumulator init with the self-loop message
//     acc[i][c] = gelu(x[i][c]) * rsqrt(deg_row[i]) * rsqrt(deg_col[i])
__global__ void k2_norm_self(const float* __restrict__ x) {
    int t = blockIdx.x * blockDim.x + threadIdx.x;
    if (t >= N_NODES * C) return;
    int i = t >> 7;
    int c = t & 127;
    float rr = rsqrtf((float)g_deg_row[i]);
    float rc = rsqrtf((float)g_deg_col[i]);
    if (c == 0) { g_rrow[i] = rr; g_rcol[i] = rc; }
    g_acc[t] = gelu_exact(x[t]) * rr * rc;
}

// K3: one warp per edge (grid-stride). W_bond cached in registers
// (16 x float4 per lane covering its 4 channels), edge_attr broadcast
// via shfl, scatter via red.global.add.v4.f32.
__global__ void __launch_bounds__(256) k3_edges(
    const float* __restrict__ x,
    const float* __restrict__ edge_attr,
    const float* __restrict__ edge_weight,
    const float* __restrict__ W_bond,
    const float* __restrict__ b_bond,
    const int*   __restrict__ ei)
{
    const int lane   = threadIdx.x & 31;
    const int warpG  = blockIdx.x * (blockDim.x >> 5) + (threadIdx.x >> 5);
    const int nWarps = gridDim.x * (blockDim.x >> 5);
    const int c0     = lane << 2;   // this lane's 4 channels

    float4 w[16];
#pragma unroll
    for (int k = 0; k < 16; k++)
        w[k] = *reinterpret_cast<const float4*>(W_bond + k * C + c0);
    const float4 bb = *reinterpret_cast<const float4*>(b_bond + c0);

    for (int e = warpG; e < N_EDGES; e += nWarps) {
        const int row = ei[e];
        const int col = ei[N_EDGES + e];
        const float s = g_rrow[row] * g_rcol[col] * edge_weight[e];
        const float a = (lane < 16) ? edge_attr[e * 16 + lane] : 0.0f;
        const float4 xv = *reinterpret_cast<const float4*>(x + row * C + c0);

        float ax = bb.x + xv.x;
        float ay = bb.y + xv.y;
        float az = bb.z + xv.z;
        float aw = bb.w + xv.w;
#pragma unroll
        for (int k = 0; k < 16; k++) {
            const float ak = __shfl_sync(0xffffffffu, a, k);
            ax = fmaf(ak, w[k].x, ax);
            ay = fmaf(ak, w[k].y, ay);
            az = fmaf(ak, w[k].z, az);
            aw = fmaf(ak, w[k].w, aw);
        }
        ax = gelu_exact(ax) * s;
        ay = gelu_exact(ay) * s;
        az = gelu_exact(az) * s;
        aw = gelu_exact(aw) * s;

        float* p = g_acc + col * C + c0;
        asm volatile("red.global.add.v4.f32 [%0], {%1,%2,%3,%4};"
                     :: "l"(p), "f"(ax), "f"(ay), "f"(az), "f"(aw)
                     : "memory");
    }
}

// K4: out = acc @ W_lin + b_lin, tiled 16 nodes per block so W_lin is
// reused 16x from L1/L2. acc tile staged in smem (broadcast reads).
__global__ void __launch_bounds__(256) k4_lin(
    const float* __restrict__ W_lin,
    const float* __restrict__ b_lin,
    float* __restrict__ out)
{
    __shared__ float a_s[16][C];
    const int tid   = threadIdx.x;
    const int node0 = blockIdx.x * 16;

    // stage 16 acc rows (2048 floats = 512 float4)
    for (int idx = tid; idx < 16 * C / 4; idx += 256) {
        reinterpret_cast<float4*>(&a_s[0][0])[idx] =
            reinterpret_cast<const float4*>(g_acc + node0 * C)[idx];
    }
    __syncthreads();

    const int c    = tid & 127;
    const int half = tid >> 7;   // 0 or 1 -> nodes [half*8, half*8+8)
    const float bl = b_lin[c];
    float accv[8];
#pragma unroll
    for (int j = 0; j < 8; j++) accv[j] = bl;

    for (int k = 0; k < C; k++) {
        const float wv = W_lin[k * C + c];
#pragma unroll
        for (int j = 0; j < 8; j++)
            accv[j] = fmaf(a_s[half * 8 + j][k], wv, accv[j]);
    }
#pragma unroll
    for (int j = 0; j < 8; j++)
        out[(node0 + half * 8 + j) * C + c] = accv[j];
}

extern "C" void kernel_launch(void* const* d_in, const int* in_sizes, int n_in,
                              void* d_out, int out_size) {
    const float* x           = (const float*)d_in[0];
    const float* edge_attr   = (const float*)d_in[1];
    const float* edge_weight = (const float*)d_in[2];
    const float* W_bond      = (const float*)d_in[3];
    const float* b_bond      = (const float*)d_in[4];
    const float* W_lin       = (const float*)d_in[5];
    const float* b_lin       = (const float*)d_in[6];
    const int*   ei          = (const int*)d_in[7];
    float* out = (float*)d_out;

    k0_init_deg<<<(N_NODES + 255) / 256, 256>>>();
    k1_deg<<<(N_EDGES + 255) / 256, 256>>>(ei);
    k2_norm_self<<<(N_NODES * C + 255) / 256, 256>>>(x);
    k3_edges<<<2048, 256>>>(x, edge_attr, edge_weight, W_bond, b_bond, ei);
    k4_lin<<<N_NODES / 16, 256>>>(W_lin, b_lin, out);
}

// round 3
// speedup vs baseline: 1.1667x; 1.1667x over previous
#include <cuda_runtime.h>
#include <cuda_bf16.h>

#define N_NODES 10000
#define N_EDGES 640000
#define C 128

// Scratch (device globals — no allocation allowed in kernel_launch)
__device__ int   g_deg_row[N_NODES];
__device__ int   g_deg_col[N_NODES];
__device__ float g_rrow[N_NODES];
__device__ float g_rcol[N_NODES];
__device__ float g_acc[N_NODES * C];

__device__ __forceinline__ float gelu_exact(float v) {
    return 0.5f * v * (1.0f + erff(v * 0.70710678118654752440f));
}

// K0: degree init = 1 (self loop)
__global__ void k0_init_deg() {
    int i = blockIdx.x * blockDim.x + threadIdx.x;
    if (i < N_NODES) { g_deg_row[i] = 1; g_deg_col[i] = 1; }
}

// K1: degree histogram over edges
__global__ void k1_deg(const int* __restrict__ ei) {
    int e = blockIdx.x * blockDim.x + threadIdx.x;
    if (e < N_EDGES) {
        atomicAdd(&g_deg_row[__ldg(ei + e)], 1);
        atomicAdd(&g_deg_col[__ldg(ei + N_EDGES + e)], 1);
    }
}

// K2: norm arrays + accumulator init with the self-loop message
__global__ void k2_norm_self(const float* __restrict__ x) {
    int t = blockIdx.x * blockDim.x + threadIdx.x;
    if (t >= N_NODES * C) return;
    int i = t >> 7;
    int c = t & 127;
    float rr = rsqrtf((float)g_deg_row[i]);
    float rc = rsqrtf((float)g_deg_col[i]);
    if (c == 0) { g_rrow[i] = rr; g_rcol[i] = rc; }
    g_acc[t] = gelu_exact(x[t]) * rr * rc;
}

// K3: one warp per edge, 2-deep software pipeline over grid-stride
// iterations so the ei[e] -> x[row] dependent load chain is hidden:
//   stage2: issue index loads for edge e+2S
//   stage1: issue x/attr/ew/norm loads for edge e+S (indices ready)
//   stage0: compute + scatter edge e (data ready)
__global__ void __launch_bounds__(256, 2) k3_edges(
    const float* __restrict__ x,
    const float* __restrict__ edge_attr,
    const float* __restrict__ edge_weight,
    const float* __restrict__ W_bond,
    const float* __restrict__ b_bond,
    const int*   __restrict__ ei)
{
    const int lane  = threadIdx.x & 31;
    const int warpG = blockIdx.x * 8 + (threadIdx.x >> 5);
    const int S     = gridDim.x * 8;
    const int c0    = lane << 2;   // this lane's 4 channels

    float4 w[16];
#pragma unroll
    for (int k = 0; k < 16; k++)
        w[k] = __ldg(reinterpret_cast<const float4*>(W_bond + k * C + c0));
    const float4 bb = __ldg(reinterpret_cast<const float4*>(b_bond + c0));

    const int e0 = warpG;
    // ---- prologue ----
    // indices for e0 (needed immediately) and e0+S (stage1 input next iter)
    int rI = 0, cI = 0;          // indices of edge e+S
    if (e0 + S < N_EDGES) { rI = __ldg(ei + e0 + S); cI = __ldg(ei + N_EDGES + e0 + S); }
    int   colC = 0;              // col of compute edge
    float4 xv0 = make_float4(0.f, 0.f, 0.f, 0.f);
    float a0 = 0.f, s0 = 0.f;
    if (e0 < N_EDGES) {
        const int r0 = __ldg(ei + e0);
        colC = __ldg(ei + N_EDGES + e0);
        xv0  = __ldg(reinterpret_cast<const float4*>(x + r0 * C + c0));
        a0   = (lane < 16) ? __ldg(edge_attr + e0 * 16 + lane) : 0.0f;
        s0   = g_rrow[r0] * g_rcol[colC] * __ldg(edge_weight + e0);
    }

    for (int e = e0; e < N_EDGES; e += S) {
        const int e1 = e + S;
        const int e2 = e + 2 * S;

        // stage2: indices for e+2S
        int rI2 = 0, cI2 = 0;
        if (e2 < N_EDGES) { rI2 = __ldg(ei + e2); cI2 = __ldg(ei + N_EDGES + e2); }

        // stage1: data for e+S using (rI, cI) loaded last iteration
        float4 xv1 = make_float4(0.f, 0.f, 0.f, 0.f);
        float a1 = 0.f, s1 = 0.f;
        if (e1 < N_EDGES) {
            xv1 = __ldg(reinterpret_cast<const float4*>(x + rI * C + c0));
            a1  = (lane < 16) ? __ldg(edge_attr + e1 * 16 + lane) : 0.0f;
            s1  = g_rrow[rI] * g_rcol[cI] * __ldg(edge_weight + e1);
        }

        // stage0: compute edge e
        float ax = bb.x + xv0.x;
        float ay = bb.y + xv0.y;
        float az = bb.z + xv0.z;
        float aw = bb.w + xv0.w;
#pragma unroll
        for (int k = 0; k < 16; k++) {
            const float ak = __shfl_sync(0xffffffffu, a0, k);
            ax = fmaf(ak, w[k].x, ax);
            ay = fmaf(ak, w[k].y, ay);
            az = fmaf(ak, w[k].z, az);
            aw = fmaf(ak, w[k].w, aw);
        }
        ax = gelu_exact(ax) * s0;
        ay = gelu_exact(ay) * s0;
        az = gelu_exact(az) * s0;
        aw = gelu_exact(aw) * s0;

        float* p = g_acc + colC * C + c0;
        asm volatile("red.global.add.v4.f32 [%0], {%1,%2,%3,%4};"
                     :: "l"(p), "f"(ax), "f"(ay), "f"(az), "f"(aw)
                     : "memory");

        // rotate pipeline registers
        colC = cI;
        xv0 = xv1; a0 = a1; s0 = s1;
        rI = rI2; cI = cI2;
    }
}

// K4: out = acc @ W_lin + b_lin, tiled 16 nodes per block.
__global__ void __launch_bounds__(256) k4_lin(
    const float* __restrict__ W_lin,
    const float* __restrict__ b_lin,
    float* __restrict__ out)
{
    __shared__ float a_s[16][C];
    const int tid   = threadIdx.x;
    const int node0 = blockIdx.x * 16;

    for (int idx = tid; idx < 16 * C / 4; idx += 256) {
        reinterpret_cast<float4*>(&a_s[0][0])[idx] =
            __ldg(reinterpret_cast<const float4*>(g_acc + node0 * C) + idx);
    }
    __syncthreads();

    const int c    = tid & 127;
    const int half = tid >> 7;
    const float bl = __ldg(b_lin + c);
    float accv[8];
#pragma unroll
    for (int j = 0; j < 8; j++) accv[j] = bl;

    for (int k = 0; k < C; k++) {
        const float wv = __ldg(W_lin + k * C + c);
#pragma unroll
        for (int j = 0; j < 8; j++)
            accv[j] = fmaf(a_s[half * 8 + j][k], wv, accv[j]);
    }
#pragma unroll
    for (int j = 0; j < 8; j++)
        out[(node0 + half * 8 + j) * C + c] = accv[j];
}

extern "C" void kernel_launch(void* const* d_in, const int* in_sizes, int n_in,
                              void* d_out, int out_size) {
    const float* x           = (const float*)d_in[0];
    const float* edge_attr   = (const float*)d_in[1];
    const float* edge_weight = (const float*)d_in[2];
    const float* W_bond      = (const float*)d_in[3];
    const float* b_bond      = (const float*)d_in[4];
    const float* W_lin       = (const float*)d_in[5];
    const float* b_lin       = (const float*)d_in[6];
    const int*   ei          = (const int*)d_in[7];
    float* out = (float*)d_out;

    k0_init_deg<<<(N_NODES + 255) / 256, 256>>>();
    k1_deg<<<(N_EDGES + 255) / 256, 256>>>(ei);
    k2_norm_self<<<(N_NODES * C + 255) / 256, 256>>>(x);
    k3_edges<<<592, 256>>>(x, edge_attr, edge_weight, W_bond, b_bond, ei);
    k4_lin<<<N_NODES / 16, 256>>>(W_lin, b_lin, out);
}